// round 11
// baseline (speedup 1.0000x reference)
#include <cuda_runtime.h>

// LIF spike recurrence, T=8:
//   mem = mem*TAU + x[t]*alpha; spike = (mem - Vth) > 0; mem = (1-spike)*mem
//
// Champion body (R2/R8/R10, 43.5us x3): batched float4 loads (__ldcs),
// register recurrence, batched __stcs stores. This round varies the ONLY
// untested knob: block size 256 -> 128. At 40 regs, warps/SM is reg-limited
// to 48 either way (occupancy invariant), but 128-thread CTAs give 2x finer
// scheduling granularity: smaller T_CTA -> smaller cross-CTA straggler
// spread at kernel end, finer tail-wave quantum. Identical per-thread work.

#define TAU 0.5f
#define THREADS 128

__global__ void __launch_bounds__(THREADS) lif_spike_kernel(
    const float* __restrict__ x,
    const float* __restrict__ alpha_p,
    const float* __restrict__ vth_p,
    float* __restrict__ out,
    int spatial /* elements per timestep */)
{
    const float alpha = __ldg(alpha_p);
    const float vth   = __ldg(vth_p);

    const int i4 = (blockIdx.x * THREADS + threadIdx.x) * 4;
    if (i4 >= spatial) return;

    // ── Front-batch all 8 timestep loads (8 independent LDG.128) ──
    float4 xt[8];
    #pragma unroll
    for (int t = 0; t < 8; t++) {
        xt[t] = __ldcs(reinterpret_cast<const float4*>(
            x + (size_t)t * (size_t)spatial + i4));
    }

    // ── Recurrence in registers ──
    float m0 = 0.f, m1 = 0.f, m2 = 0.f, m3 = 0.f;
    float4 s[8];
    #pragma unroll
    for (int t = 0; t < 8; t++) {
        m0 = m0 * TAU + xt[t].x * alpha;
        m1 = m1 * TAU + xt[t].y * alpha;
        m2 = m2 * TAU + xt[t].z * alpha;
        m3 = m3 * TAU + xt[t].w * alpha;

        s[t].x = (m0 > vth) ? 1.f : 0.f;
        s[t].y = (m1 > vth) ? 1.f : 0.f;
        s[t].z = (m2 > vth) ? 1.f : 0.f;
        s[t].w = (m3 > vth) ? 1.f : 0.f;

        // hard reset on spike
        m0 = (m0 > vth) ? 0.f : m0;
        m1 = (m1 > vth) ? 0.f : m1;
        m2 = (m2 > vth) ? 0.f : m2;
        m3 = (m3 > vth) ? 0.f : m3;
    }

    // ── Batched streaming stores ──
    #pragma unroll
    for (int t = 0; t < 8; t++) {
        __stcs(reinterpret_cast<float4*>(
            out + (size_t)t * (size_t)spatial + i4), s[t]);
    }
}

extern "C" void kernel_launch(void* const* d_in, const int* in_sizes, int n_in,
                              void* d_out, int out_size) {
    const float* x     = (const float*)d_in[0];
    const float* alpha = (const float*)d_in[1];
    const float* vth   = (const float*)d_in[2];
    float* out = (float*)d_out;

    const int total   = in_sizes[0];     // T * spatial
    const int spatial = total / 8;       // T = 8

    const int elems_per_thread = 4;
    const int blocks = (spatial + THREADS * elems_per_thread - 1) /
                       (THREADS * elems_per_thread);

    lif_spike_kernel<<<blocks, THREADS>>>(x, alpha, vth, out, spatial);
}

// round 12
// speedup vs baseline: 1.0309x; 1.0309x over previous
#include <cuda_runtime.h>

// LIF spike recurrence, T=8:
//   mem = mem*TAU + x[t]*alpha; spike = (mem - Vth) > 0; mem = (1-spike)*mem
//
// FINAL — certified champion after 11 measured rounds (43.49/43.55/43.52us
// reproduced three times; every alternative >= 44.8us).
//
// Configuration:
//   * one thread per 4 spatial positions (float4), grid 4096 x 256
//   * all 8 timestep loads front-batched (8 independent LDG.128, __ldcs)
//   * LIF recurrence entirely in registers, branchless selects
//   * 8 batched STG.128 with __stcs (streaming; zero reuse)
//
// Roofline: 268MB irreducible r/w traffic; kernel time 36-37us = ~7.3TB/s
// effective = 91%+ of the 8TB/s HBM3e spec floor (33.5us). HBM-bound.
//
// Falsified alternatives (all measured):
//   R3/R4 persistent grid; R4/R5 forced 8 CTA/SM occupancy; R5 interleaved
//   body + hints; R7 LDG.256 + L2::evict_last input pinning; R9 output
//   pinning via createpolicy/cache_hint; R11 block=128 granularity.

#define TAU 0.5f

__global__ void __launch_bounds__(256) lif_spike_kernel(
    const float* __restrict__ x,
    const float* __restrict__ alpha_p,
    const float* __restrict__ vth_p,
    float* __restrict__ out,
    int spatial /* elements per timestep */)
{
    const float alpha = __ldg(alpha_p);
    const float vth   = __ldg(vth_p);

    const int i4 = (blockIdx.x * blockDim.x + threadIdx.x) * 4;
    if (i4 >= spatial) return;

    // ── Front-batch all 8 timestep loads (8 independent LDG.128) ──
    float4 xt[8];
    #pragma unroll
    for (int t = 0; t < 8; t++) {
        xt[t] = __ldcs(reinterpret_cast<const float4*>(
            x + (size_t)t * (size_t)spatial + i4));
    }

    // ── Recurrence in registers ──
    float m0 = 0.f, m1 = 0.f, m2 = 0.f, m3 = 0.f;
    float4 s[8];
    #pragma unroll
    for (int t = 0; t < 8; t++) {
        m0 = m0 * TAU + xt[t].x * alpha;
        m1 = m1 * TAU + xt[t].y * alpha;
        m2 = m2 * TAU + xt[t].z * alpha;
        m3 = m3 * TAU + xt[t].w * alpha;

        s[t].x = (m0 > vth) ? 1.f : 0.f;
        s[t].y = (m1 > vth) ? 1.f : 0.f;
        s[t].z = (m2 > vth) ? 1.f : 0.f;
        s[t].w = (m3 > vth) ? 1.f : 0.f;

        // hard reset on spike
        m0 = (m0 > vth) ? 0.f : m0;
        m1 = (m1 > vth) ? 0.f : m1;
        m2 = (m2 > vth) ? 0.f : m2;
        m3 = (m3 > vth) ? 0.f : m3;
    }

    // ── Batched streaming stores ──
    #pragma unroll
    for (int t = 0; t < 8; t++) {
        __stcs(reinterpret_cast<float4*>(
            out + (size_t)t * (size_t)spatial + i4), s[t]);
    }
}

extern "C" void kernel_launch(void* const* d_in, const int* in_sizes, int n_in,
                              void* d_out, int out_size) {
    const float* x     = (const float*)d_in[0];
    const float* alpha = (const float*)d_in[1];
    const float* vth   = (const float*)d_in[2];
    float* out = (float*)d_out;

    const int total   = in_sizes[0];     // T * spatial
    const int spatial = total / 8;       // T = 8

    const int threads = 256;
    const int elems_per_thread = 4;
    const int blocks = (spatial + threads * elems_per_thread - 1) /
                       (threads * elems_per_thread);

    lif_spike_kernel<<<blocks, threads>>>(x, alpha, vth, out, spatial);
}